// round 13
// baseline (speedup 1.0000x reference)
#include <cuda_runtime.h>
#include <cuda_bf16.h>

// Problem dims (fixed by the dataset)
#define Hn 256
#define Bn 128
#define Tn 1000
#define Fn 20
#define On 200
#define TPB 1024         // 32 warps; 16 gather groups x 64 float4 lanes
#define NG  16

// Preprocessed weight tables (fp32, gather-friendly row layouts). ~968 KB; L2-resident.
__device__ __align__(16) float g_V1z[Hn * Hn];   // Vrec1, zero diag, [j][h]
__device__ __align__(16) float g_W2t[Hn * Hn];   // W2 transposed: [j][h] = W2[h][j]
__device__ __align__(16) float g_V2z[Hn * Hn];   // Vrec2, zero diag, [j][h]
__device__ __align__(16) float g_WoT[Hn * On];   // Wout transposed: [j][o] = Wout[o][j]
// Precomputed input drive Wx[b][t][h] = b1[h] + sum_i W1[h][i]*x[b][t][i]  (131 MB)
__device__ float g_Wx[(size_t)Bn * Tn * Hn];

__global__ void prep_tables(const float* __restrict__ Vrec1,
                            const float* __restrict__ W2,
                            const float* __restrict__ Vrec2,
                            const float* __restrict__ Wout) {
    int idx = blockIdx.x * 256 + threadIdx.x;   // 256 blocks x 256 thr = 65536 exactly
    int j = idx >> 8, h = idx & 255;
    g_V1z[idx] = (j == h) ? 0.0f : Vrec1[idx];
    g_V2z[idx] = (j == h) ? 0.0f : Vrec2[idx];
    g_W2t[idx] = W2[h * Hn + j];
    if (idx < Hn * On) {
        int jj = idx / On;
        int o  = idx - jj * On;
        g_WoT[idx] = Wout[o * Hn + jj];
    }
}

// Input-drive GEMV hoist: block = (batch, 20-step chunk), thread = neuron h.
// Same accumulation order as the in-loop version (b1 first, i ascending).
__global__ __launch_bounds__(256) void prep_wx(const float* __restrict__ x,
                                               const float* __restrict__ W1,
                                               const float* __restrict__ b1) {
    int blk = blockIdx.x;            // 0 .. Bn*50-1
    int b   = blk / 50;
    int t0  = (blk - b * 50) * 20;
    int h   = threadIdx.x;
    float w[Fn];
#pragma unroll
    for (int i = 0; i < Fn; i++) w[i] = W1[h * Fn + i];
    const float bb = b1[h];
    for (int t = t0; t < t0 + 20; t++) {
        const float* xr = x + ((size_t)b * Tn + t) * Fn;
        float acc = bb;
#pragma unroll
        for (int i = 0; i < Fn; i++) acc += w[i] * __ldg(xr + i);
        g_Wx[((size_t)b * Tn + t) * Hn + h] = acc;
    }
}

// One CTA per batch element; R1 structure (3 phases, 9 barriers), 32 warps.
__global__ __launch_bounds__(TPB) void snn_kernel(
    const float* __restrict__ beta1,
    const float* __restrict__ b2, const float* __restrict__ beta2,
    const float* __restrict__ alpha_out, const float* __restrict__ beta_out,
    float* __restrict__ out)
{
    const int tid  = threadIdx.x;
    const int b    = blockIdx.x;
    const int lane = tid & 31, warp = tid >> 5;
    const int g    = tid >> 6;        // gather group 0..15
    const int q    = tid & 63;        // float4 column lane 0..63

    __shared__ float4 pacc[TPB];                    // 16 KB partials (16 groups x 64 quads)
    __shared__ unsigned short l1[2][Hn], l2[2][Hn]; // double-buffered spike lists
    __shared__ unsigned sbal[8];
    __shared__ float redm[8], reds[8];

    const float* paccf = (const float*)pacc;

    const int pid = tid & 255;
    const float be1 = beta1[pid];
    const float b2r = b2[pid], be2 = beta2[pid];
    float aor = 0.f, bor = 0.f;
    if (tid < On) { aor = alpha_out[tid]; bor = beta_out[tid]; }

    float syn1 = 0.f, mem1 = 0.f, sp1 = 0.f;
    float syn2 = 0.f, mem2 = 0.f, sp2 = 0.f;
    float syno = 0.f, memo = 0.f, spo = 0.f, acco = 0.f;

    const float4* V1q = ((const float4*)g_V1z) + q;
    const float4* W2q = ((const float4*)g_W2t) + q;
    const float4* V2q = ((const float4*)g_V2z) + q;
    const float4* Woq = ((const float4*)g_WoT) + q;   // used only when q < 50

    const float* wxp = g_Wx + (size_t)b * Tn * Hn;
    float wx_cur = 0.f;
    if (tid < Hn) wx_cur = __ldg(wxp + pid);          // t = 0

    int c1p = 0, c2p = 0, p = 0;
    __syncthreads();

    for (int t = 0; t < Tn; t++) {
        const int n = p ^ 1;

        // prefetch next step's input drive (hides DRAM latency under the step)
        float wx_nxt = 0.f;
        if (tid < Hn && t + 1 < Tn) wx_nxt = __ldg(wxp + (t + 1) * Hn + pid);

        // ============ PHASE 1: layer-1 recurrent drive ============
        float4 a = make_float4(0.f, 0.f, 0.f, 0.f);
        {
            const unsigned short* L = l1[p];
#pragma unroll 2
            for (int k = g; k < c1p; k += NG) {
                int j = L[k];
                float4 v = __ldg(V1q + (j << 6));
                a.x += v.x; a.y += v.y; a.z += v.z; a.w += v.w;
            }
        }
        pacc[tid] = a;
        __syncthreads();                                   // 1
        unsigned bal = 0u;
        if (tid < Hn) {
            float r = 0.f;
#pragma unroll
            for (int gg = 0; gg < NG; gg++) r += paccf[gg * 256 + tid];
            syn1 = 0.95f * syn1 + (wx_cur + r);
            mem1 = be1 * mem1 + syn1 - sp1;        // detached reset: previous spike
            sp1  = (mem1 > 1.0f) ? 1.0f : 0.0f;
            bal  = __ballot_sync(0xffffffffu, sp1 > 0.5f);
            if (lane == 0) sbal[warp] = bal;
        }
        __syncthreads();                                   // 2
        int c1c;
        {
            int pre = 0, tot = 0;
#pragma unroll
            for (int w = 0; w < 8; w++) {
                int c = __popc(sbal[w]);
                if (w < warp) pre += c;
                tot += c;
            }
            if (sp1 > 0.5f)
                l1[n][pre + __popc(bal & ((1u << lane) - 1u))] = (unsigned short)tid;
            c1c = tot;
        }
        __syncthreads();                                   // 3

        // ============ PHASE 2: layer-2 drive (feedforward + recurrent) ============
        a = make_float4(0.f, 0.f, 0.f, 0.f);
        {
            const unsigned short* L = l1[n];       // current-step layer-1 spikes
#pragma unroll 2
            for (int k = g; k < c1c; k += NG) {
                int j = L[k];
                float4 v = __ldg(W2q + (j << 6));
                a.x += v.x; a.y += v.y; a.z += v.z; a.w += v.w;
            }
        }
        {
            const unsigned short* L = l2[p];       // previous-step layer-2 spikes
#pragma unroll 2
            for (int k = g; k < c2p; k += NG) {
                int j = L[k];
                float4 v = __ldg(V2q + (j << 6));
                a.x += v.x; a.y += v.y; a.z += v.z; a.w += v.w;
            }
        }
        pacc[tid] = a;
        __syncthreads();                                   // 4
        unsigned bal2 = 0u;
        if (tid < Hn) {
            float r = 0.f;
#pragma unroll
            for (int gg = 0; gg < NG; gg++) r += paccf[gg * 256 + tid];
            syn2 = 0.95f * syn2 + (b2r + r);
            mem2 = be2 * mem2 + syn2 - sp2;
            sp2  = (mem2 > 1.0f) ? 1.0f : 0.0f;
            bal2 = __ballot_sync(0xffffffffu, sp2 > 0.5f);
            if (lane == 0) sbal[warp] = bal2;
        }
        __syncthreads();                                   // 5
        int c2c;
        {
            int pre = 0, tot = 0;
#pragma unroll
            for (int w = 0; w < 8; w++) {
                int c = __popc(sbal[w]);
                if (w < warp) pre += c;
                tot += c;
            }
            if (sp2 > 0.5f)
                l2[n][pre + __popc(bal2 & ((1u << lane) - 1u))] = (unsigned short)tid;
            c2c = tot;
        }
        __syncthreads();                                   // 6

        // ============ PHASE 3: readout + softmax accumulation ============
        a = make_float4(0.f, 0.f, 0.f, 0.f);
        if (q < 50) {                               // 200 outputs = 50 float4 lanes
            const unsigned short* L = l2[n];
#pragma unroll 2
            for (int k = g; k < c2c; k += NG) {
                int j = L[k];
                float4 v = __ldg(Woq + j * 50);
                a.x += v.x; a.y += v.y; a.z += v.z; a.w += v.w;
            }
        }
        pacc[tid] = a;
        __syncthreads();                                   // 7
        float mval = -3.4e38f;
        float e = 0.f;
        if (tid < On) {
            float ot = 0.f;
#pragma unroll
            for (int gg = 0; gg < NG; gg++) ot += paccf[gg * 256 + tid];
            syno = aor * syno + ot;
            memo = bor * memo + syno - spo;
            spo  = (memo > 1.0f) ? 1.0f : 0.0f;
            mval = memo;
        }
#pragma unroll
        for (int off = 16; off; off >>= 1)
            mval = fmaxf(mval, __shfl_xor_sync(0xffffffffu, mval, off));
        if (lane == 0 && warp < 8) redm[warp] = mval;
        __syncthreads();                                   // 8
        float m = redm[0];
#pragma unroll
        for (int w = 1; w < 7; w++) m = fmaxf(m, redm[w]);  // outputs live in warps 0..6
        if (tid < On) e = __expf(memo - m);
        float sv = e;
#pragma unroll
        for (int off = 16; off; off >>= 1)
            sv += __shfl_xor_sync(0xffffffffu, sv, off);
        if (lane == 0 && warp < 8) reds[warp] = sv;
        __syncthreads();                                   // 9
        float s = reds[0];
#pragma unroll
        for (int w = 1; w < 7; w++) s += reds[w];
        if (tid < On && t > 10) acco += e / s;      // step > WARMUP (=10)

        c1p = c1c; c2p = c2c; p = n;
        wx_cur = wx_nxt;
    }

    if (tid < On) out[b * On + tid] = acco;
}

extern "C" void kernel_launch(void* const* d_in, const int* in_sizes, int n_in,
                              void* d_out, int out_size) {
    const float* x         = (const float*)d_in[0];
    const float* W1        = (const float*)d_in[1];
    const float* b1        = (const float*)d_in[2];
    const float* Vrec1     = (const float*)d_in[3];
    const float* beta1     = (const float*)d_in[4];
    const float* W2        = (const float*)d_in[5];
    const float* b2        = (const float*)d_in[6];
    const float* Vrec2     = (const float*)d_in[7];
    const float* beta2     = (const float*)d_in[8];
    const float* Wout      = (const float*)d_in[9];
    const float* alpha_out = (const float*)d_in[10];
    const float* beta_out  = (const float*)d_in[11];
    float* out = (float*)d_out;

    prep_tables<<<256, 256>>>(Vrec1, W2, Vrec2, Wout);
    prep_wx<<<Bn * 50, 256>>>(x, W1, b1);
    snn_kernel<<<Bn, TPB>>>(beta1, b2, beta2, alpha_out, beta_out, out);
}